// round 3
// baseline (speedup 1.0000x reference)
#include <cuda_runtime.h>
#include <cuda_bf16.h>
#include <cstdint>

#define U      128
#define NSEG0  32
#define NSEG1  8
#define NSEG2  32
#define NPATH  128
#define ZTOT   16384
#define METAMAX 192   // 128 paths + <=32 empty-seg dummies + 1 parity pad

// Flat path list sorted by idx_out. Each entry: {w, coeff_bits},
// w = (i0*U) | (i1*U)<<12 | o<<22. Stored as int4 = 2 paths.
__device__ int4 g_meta[METAMAX / 2];
__device__ int  g_npairs;

__global__ void tp_prep_kernel(const float* __restrict__ coeffs,
                               const int*   __restrict__ idx0,
                               const int*   __restrict__ idx1,
                               const int*   __restrict__ idx_out) {
    if (threadIdx.x != 0) return;
    int2* meta = (int2*)g_meta;
    int pos = 0;
    int last_w = 0;
    for (int o = 0; o < NSEG2; o++) {
        int cnt = 0;
        for (int p = 0; p < NPATH; p++) {
            if (idx_out[p] == o) {
                int w = (idx0[p] * U) | ((idx1[p] * U) << 12) | (o << 22);
                meta[pos++] = make_int2(w, __float_as_int(coeffs[p]));
                last_w = w;
                cnt++;
            }
        }
        if (cnt == 0) {  // dummy so every segment gets flushed (written)
            int w = (o << 22);
            meta[pos++] = make_int2(w, 0);
            last_w = w;
        }
    }
    if (pos & 1) {  // parity pad: duplicate last o with zero coeff
        meta[pos++] = make_int2(last_w, 0);
    }
    g_npairs = pos >> 1;
}

__device__ __forceinline__ void cp_async16(void* smem, const void* gmem) {
    uint32_t s = (uint32_t)__cvta_generic_to_shared(smem);
    asm volatile("cp.async.cg.shared.global [%0], [%1], 16;" :: "r"(s), "l"(gmem));
}

// One block per z-row, 128 threads = one u-lane each, 10 blocks/SM target.
__global__ __launch_bounds__(128, 10) void tp_main_kernel(
    const float* __restrict__ x0,
    const float* __restrict__ x1,
    float*       __restrict__ out)
{
    __shared__ __align__(16) float s_x0[NSEG0 * U];   // 16 KB
    __shared__ __align__(16) float s_x1[NSEG1 * U];   //  4 KB
    __shared__ int4 s_meta[METAMAX / 2];              // 1.5 KB

    const int u = threadIdx.x;
    const size_t z = blockIdx.x;

    // Stage x0/x1 rows via cp.async (no staging registers).
    const char* gx0 = (const char*)(x0 + z * (NSEG0 * U));
    const char* gx1 = (const char*)(x1 + z * (NSEG1 * U));
    #pragma unroll
    for (int k = 0; k < 8; k++)
        cp_async16((char*)s_x0 + (k * 128 + u) * 16, gx0 + (k * 128 + u) * 16);
    #pragma unroll
    for (int k = 0; k < 2; k++)
        cp_async16((char*)s_x1 + (k * 128 + u) * 16, gx1 + (k * 128 + u) * 16);
    asm volatile("cp.async.commit_group;");

    // Stage meta while cp.async is in flight.
    if (u < METAMAX / 2) s_meta[u] = g_meta[u];
    const int npairs = g_npairs;

    asm volatile("cp.async.wait_group 0;" ::: "memory");
    __syncthreads();

    float* o_row = out + z * (NSEG2 * U);

    // Flat sweep over paths (sorted by o); flush acc on segment change.
    float acc    = 0.0f;
    int   cur_oU = (s_meta[0].x >> 22) << 7;

    #pragma unroll 2
    for (int t = 0; t < npairs; t++) {
        int4 m = s_meta[t];   // 2 paths, uniform broadcast (1 wavefront)
        {
            const int   w  = m.x;
            const float c  = __int_as_float(m.y);
            const int   oU = (w >> 22) << 7;
            if (oU != cur_oU) { o_row[cur_oU + u] = acc; acc = 0.0f; cur_oU = oU; }
            const float a = s_x0[(w & 0xFFF) + u];
            const float b = s_x1[((w >> 12) & 0x3FF) + u];
            acc = fmaf(c * a, b, acc);
        }
        {
            const int   w  = m.z;
            const float c  = __int_as_float(m.w);
            const int   oU = (w >> 22) << 7;
            if (oU != cur_oU) { o_row[cur_oU + u] = acc; acc = 0.0f; cur_oU = oU; }
            const float a = s_x0[(w & 0xFFF) + u];
            const float b = s_x1[((w >> 12) & 0x3FF) + u];
            acc = fmaf(c * a, b, acc);
        }
    }
    o_row[cur_oU + u] = acc;   // final segment
}

extern "C" void kernel_launch(void* const* d_in, const int* in_sizes, int n_in,
                              void* d_out, int out_size) {
    const float* x0      = (const float*)d_in[0];
    const float* x1      = (const float*)d_in[1];
    const float* coeffs  = (const float*)d_in[2];
    const int*   idx0    = (const int*)  d_in[3];
    const int*   idx1    = (const int*)  d_in[4];
    const int*   idx_out = (const int*)  d_in[5];
    float*       out     = (float*)d_out;

    tp_prep_kernel<<<1, 32>>>(coeffs, idx0, idx1, idx_out);
    tp_main_kernel<<<ZTOT, 128>>>(x0, x1, out);
}

// round 5
// speedup vs baseline: 2.1791x; 2.1791x over previous
#include <cuda_runtime.h>
#include <cuda_bf16.h>
#include <cstdint>

#define U       128
#define NSEG0   32
#define NSEG1   8
#define NSEG2   32
#define NPATH   128
#define ZTOT    16384
#define ZB      2
#define MMAX    192   // 128 paths + <=32 dummies + parity pad

// Flat path list sorted by idx_out, all 32 segments present (dummies fill
// empties). Entry: {w, coeff_bits}; w = a_byte_off | b_byte_off<<16 | FLUSH<<31.
// Flush precedes the entry; store offset advances 512B per flush.
__device__ __align__(16) int2 g_meta[MMAX];
__device__ int  g_npairs;

#define FLUSH_BIT 0x80000000

// Parallel prep: one block, 128 threads, rank-based stable sort by idx_out.
__global__ void tp_prep_kernel(const float* __restrict__ coeffs,
                               const int*   __restrict__ idx0,
                               const int*   __restrict__ idx1,
                               const int*   __restrict__ idx_out) {
    __shared__ int   s_io[NPATH], s_i0[NPATH], s_i1[NPATH];
    __shared__ float s_c[NPATH];
    __shared__ int   s_cnt[NSEG2], s_base[NSEG2 + 1];
    __shared__ int   s_w[MMAX];
    __shared__ float s_cf[MMAX];

    const int t = threadIdx.x;
    s_io[t] = idx_out[t];
    s_i0[t] = idx0[t];
    s_i1[t] = idx1[t];
    s_c [t] = coeffs[t];
    __syncthreads();

    if (t < NSEG2) {
        int c = 0;
        for (int p = 0; p < NPATH; p++) c += (s_io[p] == t);
        s_cnt[t] = c;
    }
    __syncthreads();
    if (t == 0) {
        int off = 0;
        for (int o = 0; o < NSEG2; o++) {
            s_base[o] = off;
            off += (s_cnt[o] > 0) ? s_cnt[o] : 1;   // empty seg -> 1 dummy
        }
        s_base[NSEG2] = off;
    }
    __syncthreads();

    // Dummy entries for empty segments (coeff 0, reads smem[0] harmlessly).
    if (t < NSEG2 && s_cnt[t] == 0) { s_w[s_base[t]] = 0; s_cf[s_base[t]] = 0.f; }

    // Each path computes its stable position within its segment.
    {
        const int o = s_io[t];
        int rank = 0;
        for (int q = 0; q < t; q++) rank += (s_io[q] == o);
        const int pos = s_base[o] + rank;
        s_w [pos] = (s_i0[t] * 512) | ((s_i1[t] * 512) << 16);
        s_cf[pos] = s_c[t];
    }
    __syncthreads();

    // Segment boundaries = flush points (every segment nonempty by construction).
    if (t >= 1 && t < NSEG2) s_w[s_base[t]] |= FLUSH_BIT;
    __syncthreads();

    const int n    = s_base[NSEG2];
    const int npad = (n + 1) & ~1;
    // FIX (R4 bug): n can exceed blockDim (up to 160) -> strided write loop.
    for (int i = t; i < npad; i += NPATH) {
        int w = 0, c = 0;
        if (i < n) { w = s_w[i]; c = __float_as_int(s_cf[i]); }
        g_meta[i] = make_int2(w, c);   // pad entry: no flush, coeff 0
    }
    if (t == 0) g_npairs = npad >> 1;
}

__device__ __forceinline__ void cp_async16(void* smem, const void* gmem) {
    uint32_t s = (uint32_t)__cvta_generic_to_shared(smem);
    asm volatile("cp.async.cg.shared.global [%0], [%1], 16;" :: "r"(s), "l"(gmem));
}

// One block = 2 consecutive z-rows; 128 threads = one u-lane each, both rows.
// Rows stored as two contiguous smem copies: second-row loads use LDS
// immediate offsets (+16KB / +4KB), so per-path address math is shared.
__global__ __launch_bounds__(128, 5) void tp_main_kernel(
    const float* __restrict__ x0,
    const float* __restrict__ x1,
    float*       __restrict__ out)
{
    __shared__ __align__(16) float s_x0[ZB * NSEG0 * U];   // 32 KB
    __shared__ __align__(16) float s_x1[ZB * NSEG1 * U];   //  8 KB
    __shared__ __align__(16) int2  s_meta[MMAX];           // 1.5 KB

    const int u = threadIdx.x;
    const size_t z0 = (size_t)blockIdx.x * ZB;

    // Stage 2 z-rows (contiguous in gmem) via cp.async, 16B chunks.
    const char* gx0 = (const char*)(x0 + z0 * (NSEG0 * U));
    const char* gx1 = (const char*)(x1 + z0 * (NSEG1 * U));
    #pragma unroll
    for (int k = 0; k < 16; k++)   // 2 rows x 16KB
        cp_async16((char*)s_x0 + (k * 128 + u) * 16, gx0 + (k * 128 + u) * 16);
    #pragma unroll
    for (int k = 0; k < 4; k++)    // 2 rows x 4KB
        cp_async16((char*)s_x1 + (k * 128 + u) * 16, gx1 + (k * 128 + u) * 16);
    asm volatile("cp.async.commit_group;");

    // Stage meta while loads are in flight (L2-resident broadcast).
    if (u < MMAX / 2) ((int4*)s_meta)[u] = ((const int4*)g_meta)[u];
    const int npairs = g_npairs;

    asm volatile("cp.async.wait_group 0;" ::: "memory");
    __syncthreads();

    const char* sa = (const char*)s_x0 + u * 4;   // + a_off [+16384 row1]
    const char* sb = (const char*)s_x1 + u * 4;   // + b_off [+4096  row1]
    char* ob0 = (char*)(out + z0 * (NSEG2 * U)) + u * 4;
    char* ob1 = ob0 + NSEG2 * U * 4;
    int   off = 0;                                // advances 512B per flush
    float ax = 0.f, ay = 0.f;

#define TP_PATH(W, CBITS)                                              \
    {                                                                  \
        const int   w = (W);                                           \
        const float c = __int_as_float(CBITS);                         \
        if (w & FLUSH_BIT) {                                           \
            *(float*)(ob0 + off) = ax;                                 \
            *(float*)(ob1 + off) = ay;                                 \
            off += 512; ax = 0.f; ay = 0.f;                            \
        }                                                              \
        const char* ra = sa + (w & 0xFFFF);                            \
        const char* rb = sb + ((w >> 16) & 0x1FFF);                    \
        const float a0 = *(const float*)(ra);                          \
        const float a1 = *(const float*)(ra + NSEG0 * U * 4);          \
        const float b0 = *(const float*)(rb);                          \
        const float b1 = *(const float*)(rb + NSEG1 * U * 4);          \
        ax = fmaf(c * a0, b0, ax);                                     \
        ay = fmaf(c * a1, b1, ay);                                     \
    }

    const int4* mp = (const int4*)s_meta;
    #pragma unroll 2
    for (int t = 0; t < npairs; t++) {
        int4 m = mp[t];           // 2 paths per uniform LDS.128
        TP_PATH(m.x, m.y)
        TP_PATH(m.z, m.w)
    }
    // Final segment (31).
    *(float*)(ob0 + off) = ax;
    *(float*)(ob1 + off) = ay;
#undef TP_PATH
}

extern "C" void kernel_launch(void* const* d_in, const int* in_sizes, int n_in,
                              void* d_out, int out_size) {
    const float* x0      = (const float*)d_in[0];
    const float* x1      = (const float*)d_in[1];
    const float* coeffs  = (const float*)d_in[2];
    const int*   idx0    = (const int*)  d_in[3];
    const int*   idx1    = (const int*)  d_in[4];
    const int*   idx_out = (const int*)  d_in[5];
    float*       out     = (float*)d_out;

    tp_prep_kernel<<<1, 128>>>(coeffs, idx0, idx1, idx_out);
    tp_main_kernel<<<ZTOT / ZB, 128>>>(x0, x1, out);
}

// round 17
// speedup vs baseline: 2.5403x; 1.1658x over previous
#include <cuda_runtime.h>
#include <cuda_fp16.h>
#include <cstdint>

#define U       128
#define NSEG0   32
#define NSEG1   8
#define NSEG2   32
#define NPATH   128
#define ZTOT    16384
#define ZB      2
#define MMAX    192   // 128 paths + <=32 dummies + parity pad

// Flat path list sorted by idx_out, all 32 segments present (dummies fill
// empties). Entry: {w, coeff_bits}; w = a_byte | b_byte<<13 | FLUSH<<31,
// where a_byte = i0*256 (fp16 row stride), b_byte = i1*256.
__device__ __align__(16) int2 g_meta[MMAX];
__device__ int  g_npairs;

#define FLUSH_BIT 0x80000000

// Parallel prep: one block, 128 threads, rank-based stable sort by idx_out.
__global__ void tp_prep_kernel(const float* __restrict__ coeffs,
                               const int*   __restrict__ idx0,
                               const int*   __restrict__ idx1,
                               const int*   __restrict__ idx_out) {
    __shared__ int   s_io[NPATH], s_i0[NPATH], s_i1[NPATH];
    __shared__ float s_c[NPATH];
    __shared__ int   s_cnt[NSEG2], s_base[NSEG2 + 1];
    __shared__ int   s_w[MMAX];
    __shared__ float s_cf[MMAX];

    const int t = threadIdx.x;
    s_io[t] = idx_out[t];
    s_i0[t] = idx0[t];
    s_i1[t] = idx1[t];
    s_c [t] = coeffs[t];
    __syncthreads();

    if (t < NSEG2) {
        int c = 0;
        for (int p = 0; p < NPATH; p++) c += (s_io[p] == t);
        s_cnt[t] = c;
    }
    __syncthreads();
    if (t == 0) {
        int off = 0;
        for (int o = 0; o < NSEG2; o++) {
            s_base[o] = off;
            off += (s_cnt[o] > 0) ? s_cnt[o] : 1;   // empty seg -> 1 dummy
        }
        s_base[NSEG2] = off;
    }
    __syncthreads();

    if (t < NSEG2 && s_cnt[t] == 0) { s_w[s_base[t]] = 0; s_cf[s_base[t]] = 0.f; }

    {
        const int o = s_io[t];
        int rank = 0;
        for (int q = 0; q < t; q++) rank += (s_io[q] == o);
        const int pos = s_base[o] + rank;
        s_w [pos] = (s_i0[t] * 256) | ((s_i1[t] * 256) << 13);
        s_cf[pos] = s_c[t];
    }
    __syncthreads();

    if (t >= 1 && t < NSEG2) s_w[s_base[t]] |= FLUSH_BIT;
    __syncthreads();

    const int n    = s_base[NSEG2];
    const int npad = (n + 1) & ~1;
    for (int i = t; i < npad; i += NPATH) {  // n can exceed blockDim
        int w = 0, c = 0;
        if (i < n) { w = s_w[i]; c = __float_as_int(s_cf[i]); }
        g_meta[i] = make_int2(w, c);
    }
    if (t == 0) g_npairs = npad >> 1;
}

__device__ __forceinline__ uint32_t h2_bits(__half2 h) {
    return *reinterpret_cast<uint32_t*>(&h);
}

// One block = 2 consecutive z-rows. Inputs staged in smem as fp16 (halves the
// smem crossbar bytes, the prior binding resource). Thread u: row r = u>>6,
// half2 lane-pair l = u&63 (covers u-lanes 2l, 2l+1). fp32 accumulation.
__global__ __launch_bounds__(128, 8) void tp_main_kernel(
    const float* __restrict__ x0,
    const float* __restrict__ x1,
    float*       __restrict__ out)
{
    __shared__ __align__(16) __half s_x0h[ZB * NSEG0 * U];   // 16 KB
    __shared__ __align__(16) __half s_x1h[ZB * NSEG1 * U];   //  4 KB
    __shared__ __align__(16) int2   s_meta[MMAX];            // 1.5 KB

    const int u = threadIdx.x;
    const size_t z0 = (size_t)blockIdx.x * ZB;

    // Stage meta first (L2-resident broadcast), overlaps with loads below.
    if (u < MMAX / 2) ((int4*)s_meta)[u] = ((const int4*)g_meta)[u];
    const int npairs = g_npairs;

    // Stage 2 z-rows: LDG.128 fp32 -> convert -> STS fp16.
    {
        const float4* g0 = (const float4*)(x0 + z0 * (NSEG0 * U));  // 2048 f4
        const float4* g1 = (const float4*)(x1 + z0 * (NSEG1 * U));  //  512 f4
        uint2* s0 = (uint2*)s_x0h;
        uint2* s1 = (uint2*)s_x1h;
        #pragma unroll
        for (int k = 0; k < 16; k++) {
            const int i = k * 128 + u;
            float4 v = __ldg(&g0[i]);
            s0[i] = make_uint2(h2_bits(__floats2half2_rn(v.x, v.y)),
                               h2_bits(__floats2half2_rn(v.z, v.w)));
        }
        #pragma unroll
        for (int k = 0; k < 4; k++) {
            const int i = k * 128 + u;
            float4 v = __ldg(&g1[i]);
            s1[i] = make_uint2(h2_bits(__floats2half2_rn(v.x, v.y)),
                               h2_bits(__floats2half2_rn(v.z, v.w)));
        }
    }
    __syncthreads();

    const int r = u >> 6;       // which z-row this thread serves
    const int l = u & 63;       // half2 lane pair (u-lanes 2l, 2l+1)
    const char* sa = (const char*)s_x0h + r * (NSEG0 * U * 2) + l * 4;
    const char* sb = (const char*)s_x1h + r * (NSEG1 * U * 2) + l * 4;
    char* ob = (char*)(out + (z0 + r) * (NSEG2 * U)) + l * 8;
    int    off = 0;             // advances 512 B (one segment) per flush
    float2 acc = make_float2(0.f, 0.f);

#define TP_PATH(W, CBITS)                                              \
    {                                                                  \
        const int   w = (W);                                           \
        const float c = __int_as_float(CBITS);                         \
        if (w & FLUSH_BIT) {                                           \
            *(float2*)(ob + off) = acc;                                \
            off += 512; acc = make_float2(0.f, 0.f);                   \
        }                                                              \
        __half2 a = *(const __half2*)(sa + (w & 0x1FFF));              \
        __half2 b = *(const __half2*)(sb + ((w >> 13) & 0x7FF));       \
        float2  p = __half22float2(__hmul2(a, b));                     \
        acc.x = fmaf(c, p.x, acc.x);                                   \
        acc.y = fmaf(c, p.y, acc.y);                                   \
    }

    const int4* mp = (const int4*)s_meta;
    #pragma unroll 2
    for (int t = 0; t < npairs; t++) {
        int4 m = mp[t];            // 2 paths per uniform LDS.128
        TP_PATH(m.x, m.y)
        TP_PATH(m.z, m.w)
    }
    *(float2*)(ob + off) = acc;    // final segment (31)
#undef TP_PATH
}

extern "C" void kernel_launch(void* const* d_in, const int* in_sizes, int n_in,
                              void* d_out, int out_size) {
    const float* x0      = (const float*)d_in[0];
    const float* x1      = (const float*)d_in[1];
    const float* coeffs  = (const float*)d_in[2];
    const int*   idx0    = (const int*)  d_in[3];
    const int*   idx1    = (const int*)  d_in[4];
    const int*   idx_out = (const int*)  d_in[5];
    float*       out     = (float*)d_out;

    tp_prep_kernel<<<1, 128>>>(coeffs, idx0, idx1, idx_out);
    tp_main_kernel<<<ZTOT / ZB, 128>>>(x0, x1, out);
}